// round 5
// baseline (speedup 1.0000x reference)
#include <cuda_runtime.h>
#include <cuda_bf16.h>

#define NL 51        // NUM_LABELS
#define LS 53        // LABEL_SIZE
#define LPAD 56      // padded to multiple of 4
#define START_IDX 51
#define END_IDX 52

typedef unsigned long long u64;

__device__ __forceinline__ u64 pk2(float lo, float hi) {
    u64 r;
    asm("mov.b64 %0, {%1,%2};" : "=l"(r) : "f"(lo), "f"(hi));
    return r;
}
__device__ __forceinline__ void upk2(float& lo, float& hi, u64 v) {
    asm("mov.b64 {%0,%1}, %2;" : "=f"(lo), "=f"(hi) : "l"(v));
}
__device__ __forceinline__ void fma2(u64& d, u64 a, u64 b) {
    asm("fma.rn.f32x2 %0, %1, %2, %0;" : "+l"(d) : "l"(a), "l"(b));
}
__device__ __forceinline__ u64 add2(u64 a, u64 b) {
    u64 r;
    asm("add.rn.f32x2 %0, %1, %2;" : "=l"(r) : "l"(a), "l"(b));
    return r;
}

__global__ __launch_bounds__(64, 8)
void crf_fwd_kernel(const float* __restrict__ logits,
                    const int*   __restrict__ labels,
                    const int*   __restrict__ lens,
                    const float* __restrict__ transition,
                    float* __restrict__ out, int S)
{
    __shared__ float sh_T[LS * LS];
    __shared__ __align__(16) float sh_e[2][LPAD];
    __shared__ float sh_C[2];
    __shared__ float sh_a[64];
    __shared__ float sh_red[64];

    const int b = blockIdx.x;
    const int j = threadIdx.x;
    const int len = lens[b];

    // ---- load transition into shared ----
    for (int k = j; k < LS * LS; k += 64) sh_T[k] = transition[k];
    if (j < LPAD) { sh_e[0][j] = 0.f; sh_e[1][j] = 0.f; }
    __syncthreads();

    // ---- per-thread row E = exp(T[j,:] - rowmax), packed into f32x2 pairs ----
    u64 Erp[LPAD / 2];
    float rmax = 0.f;
    if (j < LS) {
        rmax = -1e30f;
        #pragma unroll
        for (int i = 0; i < LS; i++) rmax = fmaxf(rmax, sh_T[j * LS + i]);
        float Er[LPAD];
        #pragma unroll
        for (int i = 0; i < LS; i++) Er[i] = __expf(sh_T[j * LS + i] - rmax);
        #pragma unroll
        for (int i = LS; i < LPAD; i++) Er[i] = 0.f;
        #pragma unroll
        for (int q = 0; q < LPAD / 2; q++) Erp[q] = pk2(Er[2 * q], Er[2 * q + 1]);
    } else {
        #pragma unroll
        for (int q = 0; q < LPAD / 2; q++) Erp[q] = 0ull;
    }

    // ---- gold score partials (unary + binary), parallel over t ----
    const float* Lb  = logits + (size_t)b * S * NL;
    const int*   lab = labels + (size_t)b * S;
    {
        float g = 0.f;
        for (int t = j; t < len; t += 64) {
            int lt = lab[t];
            g += Lb[(size_t)t * NL + lt];
            int lp = (t == 0) ? START_IDX : lab[t - 1];
            g += sh_T[lt * LS + lp];
        }
        if (j == 0) g += sh_T[END_IDX * LS + lab[len - 1]];
        sh_red[j] = g;
    }
    // (sh_red read only after later barriers)

    // ---- forward recurrence ----
    // Exact running normalizer: row T[START,:] == +100 and lg[START] == -100,
    // so alpha[START] evolves as exactly lse_i(alpha_i). Thread START publishes
    // its alpha each step through shared; offset C is 2 steps stale (drift << 87).
    float a = (j < LS) ? ((j == START_IDX) ? 0.f : -100.f) : -1e30f;
    float C = 0.f;

    // distance-2 logit prefetch; lanes >= NL are the -100 padding of logits_p
    float lg_cur, lg_nxt;
    {
        int t1 = (1 < S) ? 1 : 0;
        lg_cur = (j < NL) ? Lb[j] : -100.f;
        lg_nxt = (j < NL) ? Lb[(size_t)t1 * NL + j] : -100.f;
    }

    int buf = 0;
    for (int t = 0; t < len; t++) {
        float e = __expf(a - C);
        if (j < LPAD) sh_e[buf][j] = e;
        if (j == START_IDX) sh_C[buf] = a;   // running lse(alpha) from previous step
        __syncthreads();

        float newC = sh_C[buf];

        // dot over i: 14 x LDS.128 broadcast, 28 packed FFMA2, 4 packed accumulators
        u64 ac0 = 0ull, ac1 = 0ull, ac2 = 0ull, ac3 = 0ull;
        const ulonglong2* p = (const ulonglong2*)sh_e[buf];
        #pragma unroll
        for (int q = 0; q < LPAD / 4; q += 2) {
            ulonglong2 v0 = p[q];
            fma2(ac0, v0.x, Erp[2 * q + 0]);
            fma2(ac1, v0.y, Erp[2 * q + 1]);
            ulonglong2 v1 = p[q + 1];
            fma2(ac2, v1.x, Erp[2 * q + 2]);
            fma2(ac3, v1.y, Erp[2 * q + 3]);
        }
        u64 acc = add2(add2(ac0, ac1), add2(ac2, ac3));
        float slo, shi;
        upk2(slo, shi, acc);
        float s = slo + shi;

        float lg = lg_cur;
        lg_cur = lg_nxt;
        {   // prefetch t+2 (clamped; unused when beyond len)
            int tt = t + 2; if (tt > S - 1) tt = S - 1;
            lg_nxt = (j < NL) ? Lb[(size_t)tt * NL + j] : -100.f;
        }

        a = lg + C + rmax + __logf(s);
        C = newC;
        buf ^= 1;
    }

    // ---- norm = lse_j(alpha[j] + T[END, j]); combine with gold and write ----
    sh_a[j] = (j < LS) ? (a + sh_T[END_IDX * LS + j]) : -1e30f;
    __syncthreads();
    if (j == 0) {
        float m = -1e30f;
        #pragma unroll
        for (int i = 0; i < LS; i++) m = fmaxf(m, sh_a[i]);
        float ssum = 0.f;
        #pragma unroll
        for (int i = 0; i < LS; i++) ssum += __expf(sh_a[i] - m);
        float norm = m + __logf(ssum);

        float gold = 0.f;
        #pragma unroll
        for (int i = 0; i < 64; i++) gold += sh_red[i];

        out[b] = gold - norm;
    }
}

extern "C" void kernel_launch(void* const* d_in, const int* in_sizes, int n_in,
                              void* d_out, int out_size)
{
    const float* logits     = (const float*)d_in[0];
    const int*   labels     = (const int*)  d_in[1];
    const int*   lens       = (const int*)  d_in[2];
    const float* transition = (const float*)d_in[3];
    float* out = (float*)d_out;

    int B = out_size;                 // 256
    int S = in_sizes[1] / B;          // labels is (B, S) -> 2048

    crf_fwd_kernel<<<B, 64>>>(logits, labels, lens, transition, out, S);
}

// round 6
// speedup vs baseline: 1.3292x; 1.3292x over previous
#include <cuda_runtime.h>
#include <cuda_bf16.h>

#define NL 51        // NUM_LABELS
#define LS 53        // LABEL_SIZE
#define LPAD 56      // padded to multiple of 4
#define START_IDX 51
#define END_IDX 52

__global__ __launch_bounds__(64, 8)
void crf_fwd_kernel(const float* __restrict__ logits,
                    const int*   __restrict__ labels,
                    const int*   __restrict__ lens,
                    const float* __restrict__ transition,
                    float* __restrict__ out, int S)
{
    __shared__ float sh_T[LS * LS];
    __shared__ __align__(16) float sh_e[2][LPAD];
    __shared__ float sh_C[2];
    __shared__ float sh_a[64];
    __shared__ float sh_red[64];

    const int b = blockIdx.x;
    const int j = threadIdx.x;
    const int len = lens[b];

    // ---- transition into shared ----
    for (int k = j; k < LS * LS; k += 64) sh_T[k] = transition[k];
    __syncthreads();

    // ---- per-thread row of E = exp(T[j,:] - rowmax), kept in registers ----
    float Er[LPAD];
    float rmax = 0.f;
    if (j < LS) {
        rmax = -1e30f;
        #pragma unroll
        for (int i = 0; i < LS; i++) rmax = fmaxf(rmax, sh_T[j * LS + i]);
        #pragma unroll
        for (int i = 0; i < LS; i++) Er[i] = __expf(sh_T[j * LS + i] - rmax);
        #pragma unroll
        for (int i = LS; i < LPAD; i++) Er[i] = 0.f;
    } else {
        rmax = 0.f;
        #pragma unroll
        for (int i = 0; i < LPAD; i++) Er[i] = 0.f;
    }

    // ---- gold score partials (unary + binary), parallel over t ----
    const float* Lb  = logits + (size_t)b * S * NL;
    const int*   lab = labels + (size_t)b * S;
    {
        float g = 0.f;
        for (int t = j; t < len; t += 64) {
            int lt = lab[t];
            g += Lb[(size_t)t * NL + lt];
            int lp = (t == 0) ? START_IDX : lab[t - 1];
            g += sh_T[lt * LS + lp];
        }
        if (j == 0) g += sh_T[END_IDX * LS + lab[len - 1]];
        sh_red[j] = g;
    }
    // (sh_red is read only after the scan's many barriers)

    // ---- exp-domain forward recurrence ----
    // Invariant: u_j = exp(alpha_j - C); thread START broadcasts alpha_START
    // (== exact running lse of alpha, since T[START,:] == +100 and
    // logits_p[START] == -100) as the next offset. Offset is 2 steps stale;
    // drift << 87, so all exps stay in range.
    float a0 = (j < LS) ? ((j == START_IDX) ? 0.f : -100.f) : -1e30f;
    float u  = __expf(a0);               // 1 for START, ~0 elsewhere
    if (j < LPAD) sh_e[0][j] = u;
    if (j == 0) sh_C[0] = 0.f;           // alpha_START = 0
    float C = 0.f;

    // distance-3 prefetch of lgr = logit + rmax (lanes >= NL: -100 padding)
    float lgr0, lgr1, lgr2;
    {
        int t1 = (1 < S) ? 1 : 0;
        int t2 = (2 < S) ? 2 : S - 1;
        lgr0 = ((j < NL) ? Lb[j] : -100.f) + rmax;
        lgr1 = ((j < NL) ? Lb[(size_t)t1 * NL + j] : -100.f) + rmax;
        lgr2 = ((j < NL) ? Lb[(size_t)t2 * NL + j] : -100.f) + rmax;
    }

    int buf = 0;
    for (int t = 0; t < len; t++) {
        __syncthreads();                 // publishes sh_e[buf], sh_C[buf]

        float newC = sh_C[buf];
        float f = __expf(lgr0 + (C - newC));   // issued early; overlaps the dot

        // rotate prefetch, fetch t+3 (clamped)
        lgr0 = lgr1; lgr1 = lgr2;
        {
            int tt = t + 3; if (tt > S - 1) tt = S - 1;
            lgr2 = ((j < NL) ? Lb[(size_t)tt * NL + j] : -100.f) + rmax;
        }

        // dot over i: 14 x float4 broadcast loads, 4 independent accumulators
        float s0 = 0.f, s1 = 0.f, s2 = 0.f, s3 = 0.f;
        const float4* p = (const float4*)sh_e[buf];
        #pragma unroll
        for (int q = 0; q < LPAD / 4; q++) {
            float4 v = p[q];
            s0 += v.x * Er[4 * q + 0];
            s1 += v.y * Er[4 * q + 1];
            s2 += v.z * Er[4 * q + 2];
            s3 += v.w * Er[4 * q + 3];
        }
        float s = (s0 + s1) + (s2 + s3);

        u = s * f;                        // u' = exp(alpha' - newC)
        int nb = buf ^ 1;
        if (j < LPAD) sh_e[nb][j] = u;
        if (j == START_IDX) sh_C[nb] = C + __logf(s);  // alpha'_START (exact lse)
        C = newC;
        buf = nb;
    }

    // ---- norm = lse_j(alpha_j + T[END, j]); combine with gold and write ----
    // alpha_j = C + log(u); u == 0 -> -inf, contributes 0 (START lane keeps it finite)
    sh_a[j] = (j < LS) ? (C + __logf(u) + sh_T[END_IDX * LS + j]) : -1e30f;
    __syncthreads();
    if (j == 0) {
        float m = -1e30f;
        #pragma unroll
        for (int i = 0; i < LS; i++) m = fmaxf(m, sh_a[i]);
        float ssum = 0.f;
        #pragma unroll
        for (int i = 0; i < LS; i++) ssum += __expf(sh_a[i] - m);
        float norm = m + __logf(ssum);

        float gold = 0.f;
        #pragma unroll
        for (int i = 0; i < 64; i++) gold += sh_red[i];

        out[b] = gold - norm;
    }
}

extern "C" void kernel_launch(void* const* d_in, const int* in_sizes, int n_in,
                              void* d_out, int out_size)
{
    const float* logits     = (const float*)d_in[0];
    const int*   labels     = (const int*)  d_in[1];
    const int*   lens       = (const int*)  d_in[2];
    const float* transition = (const float*)d_in[3];
    float* out = (float*)d_out;

    int B = out_size;                 // 256
    int S = in_sizes[1] / B;          // labels is (B, S) -> 2048

    crf_fwd_kernel<<<B, 64>>>(logits, labels, lens, transition, out, S);
}